// round 4
// baseline (speedup 1.0000x reference)
#include <cuda_runtime.h>
#include <cstdint>

// ---------------------------------------------------------------------------
// TContextGGANN_39805756899562
//
// Math recap (verified R1-R3, rel_err = 0.0 exactly): the reference network
// has an exact fixed point at zero — hidden states start at zero, every
// message is elementwise-gated by a hidden state, GRU maps (a=0,h=0)->0
// bit-exactly, attention sees Q=K=V=0. Output is identically zero; the
// kernel is a pure 64 MiB zero-fill of d_out.
//
// R2/R3 established an SM-side STG ceiling at ~2900 B/cyc (~half the 6300
// B/cyc LTS load cap): L2=48%, L1=57% invariant under grid/unroll changes.
// R4 switches the write PATH: TMA bulk stores (cp.async.bulk
// global <- shared::cta). Each block zeroes 32 KB of SMEM once, then streams
// it to its 64 KB slice of d_out via bulk-group stores.
// ---------------------------------------------------------------------------

static __device__ __forceinline__ uint32_t smem_u32(const void* p) {
    uint32_t a;
    asm("{ .reg .u64 t; cvta.to.shared.u64 t, %1; cvt.u32.u64 %0, t; }"
        : "=r"(a) : "l"(p));
    return a;
}

static constexpr int SMEM_BYTES = 32768;            // one 32 KB zero tile
static constexpr long long BYTES_PER_BLOCK = 65536; // 2 bulk stores per block

__global__ void __launch_bounds__(128) tcg_tma_zero(char* __restrict__ out,
                                                    long long total_bytes) {
    __shared__ __align__(1024) char buf[SMEM_BYTES];

    // Zero the SMEM tile (STS.128, SM-internal, trivial cost).
    const float4 z = make_float4(0.f, 0.f, 0.f, 0.f);
    for (int i = threadIdx.x * 16; i < SMEM_BYTES; i += blockDim.x * 16)
        *reinterpret_cast<float4*>(buf + i) = z;
    __syncthreads();

    if (threadIdx.x == 0) {
        // Make generic-proxy SMEM writes visible to the async (TMA) proxy.
        asm volatile("fence.proxy.async.shared::cta;" ::: "memory");

        uint32_t sbuf = smem_u32(buf);
        long long start = (long long)blockIdx.x * BYTES_PER_BLOCK;
        long long end   = start + BYTES_PER_BLOCK;
        if (end > total_bytes) end = total_bytes;

        for (long long off = start; off < end; off += SMEM_BYTES) {
            long long rem = end - off;
            uint32_t size = (uint32_t)(rem < SMEM_BYTES ? rem : SMEM_BYTES);
            size &= ~15u;  // bulk copies must be multiples of 16 bytes
            if (size) {
                asm volatile(
                    "cp.async.bulk.global.shared::cta.bulk_group [%0], [%1], %2;"
                    :: "l"(out + off), "r"(sbuf), "r"(size)
                    : "memory");
            }
        }
        asm volatile("cp.async.bulk.commit_group;" ::: "memory");
        asm volatile("cp.async.bulk.wait_group 0;" ::: "memory");
    }
}

// Scalar tail for any bytes not coverable by 16B-multiple bulk stores
// (never triggers for this problem: out_size*4 is 16B-aligned).
__global__ void tcg_zero_tail_bytes(char* __restrict__ out, long long start,
                                    long long n) {
    long long i = start + (long long)blockIdx.x * blockDim.x + threadIdx.x;
    if (i < n) out[i] = 0;
}

extern "C" void kernel_launch(void* const* d_in, const int* in_sizes, int n_in,
                              void* d_out, int out_size) {
    (void)d_in; (void)in_sizes; (void)n_in;

    char* out = (char*)d_out;
    long long total_bytes = (long long)out_size * 4;   // fp32 output
    long long bulk_bytes  = total_bytes & ~15LL;

    if (bulk_bytes > 0) {
        int blocks = (int)((bulk_bytes + BYTES_PER_BLOCK - 1) / BYTES_PER_BLOCK);
        tcg_tma_zero<<<blocks, 128>>>(out, bulk_bytes);  // 1024 blocks here
    }
    if (bulk_bytes < total_bytes) {
        long long rem = total_bytes - bulk_bytes;
        int blocks = (int)((rem + 127) / 128);
        tcg_zero_tail_bytes<<<blocks, 128>>>(out, bulk_bytes, total_bytes);
    }
}

// round 5
// speedup vs baseline: 1.0021x; 1.0021x over previous
#include <cuda_runtime.h>

// ---------------------------------------------------------------------------
// TContextGGANN_39805756899562
//
// Math recap (verified R1-R4, rel_err = 0.0 exactly): the reference network
// has an exact fixed point at zero — all hidden states start at zero, every
// message is elementwise-gated by a hidden state, the GRU maps (a=0,h=0)->0
// bit-exactly, and the final attention sees Q=K=V=0. The output is
// identically zero, so the kernel reduces to a 64 MiB zero-fill of d_out.
//
// Bandwidth post-mortem (R2-R4): STG.128 grid-stride (11.5 us) and TMA bulk
// stores (13.5 us) both converge to ~5.8 TB/s = ~2930 B/cyc — the L2 write-
// acceptance ceiling (192 slices x ~16 B/cyc, half the load-path rate).
// The device-time floor for 64 MiB of writes is ~11.2 us; further STG/TMA
// tuning is dead. R5 targets the remaining ~1.5 us of launch overhead by
// using a single cudaMemsetAsync, captured as one graph memset node
// (no kernel-launch setup, no dead tail branch).
// ---------------------------------------------------------------------------

extern "C" void kernel_launch(void* const* d_in, const int* in_sizes, int n_in,
                              void* d_out, int out_size) {
    (void)d_in; (void)in_sizes; (void)n_in;
    // fp32 output: out_size elements * 4 bytes. Async on the capture stream
    // (legacy default stream) -> recorded as a single memset node.
    cudaMemsetAsync(d_out, 0, (size_t)out_size * sizeof(float), 0);
}

// round 6
// speedup vs baseline: 1.1597x; 1.1572x over previous
#include <cuda_runtime.h>

// ---------------------------------------------------------------------------
// TContextGGANN_39805756899562
//
// Math (verified R1-R5, rel_err = 0.0 exactly): the reference network has an
// exact fixed point at zero — all hidden states start at zero, every message
// is elementwise-gated by a hidden state, the GRU maps (a=0,h=0)->0 bit-
// exactly across all LOOPS, and the final attention sees Q=K=V=0. The output
// is identically zero; the kernel reduces to a 64 MiB zero-fill of d_out.
//
// Bandwidth post-mortem (R2-R5): four write paths converge at/above the same
// wall —
//   STG.128 4096x4   : 11.46 us  (5.86 TB/s)   <- best
//   STG.128 1024x16  : 11.74 us
//   TMA bulk stores  : 13.54 us
//   driver memset    : ~13.5 us (dur 15.1)
// i.e. the L2 write-acceptance ceiling (~2970 B/cyc ~= 192 slices x 16 B/cyc,
// half the load-path rate; path-independent). R2's kernel is at ~100% of
// this floor. R6 keeps that shape with one micro-probe along the measured
// grid gradient: 8192 blocks x 2 STG.128/thread.
// ---------------------------------------------------------------------------

__global__ void __launch_bounds__(256) tcg_zero2(float4* __restrict__ out, int n4) {
    int t = blockIdx.x * blockDim.x + threadIdx.x;
    int total = gridDim.x * blockDim.x;
    const float4 z = make_float4(0.0f, 0.0f, 0.0f, 0.0f);
    #pragma unroll
    for (int k = 0; k < 2; ++k) {
        int i = t + k * total;
        if (i < n4) out[i] = z;
    }
}

__global__ void tcg_zero_tail(float* __restrict__ out, int start, int n) {
    int i = start + blockIdx.x * blockDim.x + threadIdx.x;
    if (i < n) out[i] = 0.0f;
}

extern "C" void kernel_launch(void* const* d_in, const int* in_sizes, int n_in,
                              void* d_out, int out_size) {
    (void)d_in; (void)in_sizes; (void)n_in;

    float* out = (float*)d_out;
    int n  = out_size;            // 16,777,216 fp32 for this problem
    int n4 = n >> 2;              // float4 chunks; d_out is 256B-aligned
    int rem_start = n4 << 2;

    if (n4 > 0) {
        const int threads = 256;
        const int per_thread = 2;
        int blocks = (n4 + threads * per_thread - 1) / (threads * per_thread);
        tcg_zero2<<<blocks, threads>>>((float4*)out, n4);   // 8192 blocks here
    }
    if (rem_start < n) {          // never launched for n % 4 == 0
        int rem = n - rem_start;
        int blocks = (rem + 127) / 128;
        tcg_zero_tail<<<blocks, 128>>>(out, rem_start, n);
    }
}

// round 7
// speedup vs baseline: 1.1830x; 1.0201x over previous
#include <cuda_runtime.h>

// ---------------------------------------------------------------------------
// TContextGGANN_39805756899562  —  FINAL
//
// Algorithmic result (R1, re-verified every round, rel_err = 0.0 exactly):
// the reference network has an exact fixed point at zero. All four hidden
// states initialize to zeros; every message is elementwise-gated by a hidden
// state (enc * h == 0); the GRU update (1-z)*h + z*tanh(a@Wox.T + (r*h)@Woh.T)
// maps (a=0, h=0) to exactly 0 (every term is a multiply by exact 0.0, no
// rounding enters); this holds across all LOOPS iterations; the final
// attention then sees Q=K=V=0, so A@V = 0. The returned (h_e, h_l, h_i, h_m)
// are identically zero for any inputs — the ~2e11 FLOPs of the apparent
// compute graph are dead code. The kernel reduces to a 64 MiB zero-fill of
// the poisoned d_out.
//
// Hardware result (R2-R6): the zero-fill is bounded by the L2 write-
// acceptance ceiling, ~2970 B/cyc (~5.86 TB/s @NAT) = 192 slices x ~16 B/cyc,
// half the 6300 B/cyc load-path cap, and PATH-INDEPENDENT:
//   STG.128  4096 x 4/thr : 11.46 us   <- this kernel (best)
//   STG.128  8192 x 2/thr : 11.58 us
//   STG.128  1024 x 16/thr: 11.74 us
//   TMA bulk stores       : 13.54 us
//   driver memset node    : ~13.5 us
// The remaining dur-kernel gap (~1.4 us) is graph-replay overhead,
// node-type-independent (R5). This kernel sits at ~100% of the write floor.
// ---------------------------------------------------------------------------

__global__ void __launch_bounds__(256) tcg_zero4(float4* __restrict__ out, int n4) {
    int t = blockIdx.x * blockDim.x + threadIdx.x;
    int total = gridDim.x * blockDim.x;
    const float4 z = make_float4(0.0f, 0.0f, 0.0f, 0.0f);
    // 4 coalesced STG.128 per thread; fully unrolled, predicated bounds.
    #pragma unroll
    for (int k = 0; k < 4; ++k) {
        int i = t + k * total;
        if (i < n4) out[i] = z;
    }
}

__global__ void tcg_zero_tail(float* __restrict__ out, int start, int n) {
    int i = start + blockIdx.x * blockDim.x + threadIdx.x;
    if (i < n) out[i] = 0.0f;
}

extern "C" void kernel_launch(void* const* d_in, const int* in_sizes, int n_in,
                              void* d_out, int out_size) {
    (void)d_in; (void)in_sizes; (void)n_in;

    float* out = (float*)d_out;
    int n  = out_size;            // 16,777,216 fp32 for this problem
    int n4 = n >> 2;              // float4 chunks; d_out is 256B-aligned
    int rem_start = n4 << 2;

    if (n4 > 0) {
        const int threads = 256;
        const int per_thread = 4;
        int blocks = (n4 + threads * per_thread - 1) / (threads * per_thread);
        tcg_zero4<<<blocks, threads>>>((float4*)out, n4);   // 4096 blocks here
    }
    if (rem_start < n) {          // never launched for n % 4 == 0
        int rem = n - rem_start;
        int blocks = (rem + 127) / 128;
        tcg_zero_tail<<<blocks, 128>>>(out, rem_start, n);
    }
}